// round 8
// baseline (speedup 1.0000x reference)
#include <cuda_runtime.h>
#include <cstdint>
#include <cstddef>

// Problem constants (fixed by the reference's setup_inputs)
#define B_   2
#define S_   2048
#define H_   256
#define NS_  512
#define NR_  512
#define DIN  768    // 3*H
#define DFF  3072   // 4*DIN
#define NBLK (S_ / 16)   // 128 block-maxima per batch row
#define H4   (H_ / 4)    // 64 float4 per channel row
#define KSPLIT 8
#define MN   ((size_t)B_ * NR_ * H_)     // 524288 output elems

// Scratch (static device globals: allocation-free per harness rules)
__device__ float g_rel[(size_t)B_ * NR_ * DIN];        // 6 MB   rel_reps (tf32-rounded)
__device__ float g_h[(size_t)B_ * NR_ * DFF];          // 24 MB  hidden (tf32-rounded)
__device__ float g_blkmax[(size_t)B_ * NBLK * H_];     // 256 KB 16-token block maxima
__device__ float g_part[(size_t)KSPLIT * MN];          // 16 MB  split-K partials
__device__ float g_w1r[(size_t)DIN * DFF];             // 9.4 MB W1 tf32-rounded
__device__ float g_w2r[(size_t)DFF * H_];              // 3 MB   W2 tf32-rounded

__device__ __forceinline__ uint32_t f2tf32(float f) {
    uint32_t r;
    asm("cvt.rna.tf32.f32 %0, %1;" : "=r"(r) : "f"(f));
    return r;
}
__device__ __forceinline__ float tf32r(float f) { return __uint_as_float(f2tf32(f)); }

__device__ __forceinline__ float4 f4max(float4 a, float4 b) {
    return make_float4(fmaxf(a.x, b.x), fmaxf(a.y, b.y),
                       fmaxf(a.z, b.z), fmaxf(a.w, b.w));
}

// ---------------------------------------------------------------------------
// Weight pre-round: w_out = tf32_round(w_in), float4 vectorized.
// ---------------------------------------------------------------------------
__global__ void k_round(const float* __restrict__ in, float* __restrict__ out) {
    const size_t i = ((size_t)blockIdx.x * blockDim.x + threadIdx.x) * 4;
    float4 v = *(const float4*)(in + i);
    v.x = tf32r(v.x); v.y = tf32r(v.y); v.z = tf32r(v.z); v.w = tf32r(v.w);
    *(float4*)(out + i) = v;
}

// ---------------------------------------------------------------------------
// Kernel 0: per-16-token block maxima of token_reps. 64 threads x float4.
// ---------------------------------------------------------------------------
__global__ void k_blkmax(const float* __restrict__ tok) {
    const int blk = blockIdx.x;
    const float4* p = (const float4*)(tok + (size_t)blk * 16 * H_) + threadIdx.x;
    float4 a0 = p[0];
    float4 a1 = p[H4];
    #pragma unroll
    for (int i = 2; i < 16; i += 2) {
        a0 = f4max(a0, p[(size_t)i * H4]);
        a1 = f4max(a1, p[(size_t)(i + 1) * H4]);
    }
    ((float4*)(g_blkmax + (size_t)blk * H_))[threadIdx.x] = f4max(a0, a1);
}

// ---------------------------------------------------------------------------
// Kernel 1: rel_reps = [head | tail | context-maxpool], tf32-rounded at store.
// 64 threads/relation, float4 channels, 2 independent max-accumulators and
// manually unrolled bodies so loads batch ahead of the dependent fmax chain
// (the R7 profile showed this kernel is load-latency-chain bound).
// ---------------------------------------------------------------------------
struct Acc2 { float4 a0, a1; };

__device__ __forceinline__ void scan_tokens(Acc2& ac, const float4* tb4,
                                            int t0, int t1) {
    int t = t0;
    for (; t + 2 <= t1; t += 2) {
        float4 v0 = tb4[(size_t)t * H4];
        float4 v1 = tb4[(size_t)(t + 1) * H4];
        ac.a0 = f4max(ac.a0, v0);
        ac.a1 = f4max(ac.a1, v1);
    }
    if (t < t1) ac.a0 = f4max(ac.a0, tb4[(size_t)t * H4]);
}

__device__ __forceinline__ void scan_blocks(Acc2& ac, const float4* bb4,
                                            int j0, int j1) {
    int j = j0;
    for (; j + 4 <= j1; j += 4) {
        float4 v0 = bb4[(size_t)j * H4];
        float4 v1 = bb4[(size_t)(j + 1) * H4];
        float4 v2 = bb4[(size_t)(j + 2) * H4];
        float4 v3 = bb4[(size_t)(j + 3) * H4];
        ac.a0 = f4max(ac.a0, v0);
        ac.a1 = f4max(ac.a1, v1);
        ac.a0 = f4max(ac.a0, v2);
        ac.a1 = f4max(ac.a1, v3);
    }
    for (; j + 2 <= j1; j += 2) {
        float4 v0 = bb4[(size_t)j * H4];
        float4 v1 = bb4[(size_t)(j + 1) * H4];
        ac.a0 = f4max(ac.a0, v0);
        ac.a1 = f4max(ac.a1, v1);
    }
    if (j < j1) ac.a0 = f4max(ac.a0, bb4[(size_t)j * H4]);
}

__global__ void __launch_bounds__(64)
k_rel(const float* __restrict__ tok,
      const float* __restrict__ spans,
      const int* __restrict__ span_ids,
      const int* __restrict__ rel_ids,
      const float* __restrict__ negp) {
    const int br = blockIdx.x;           // b*NR + r
    const int b = br >> 9;
    const int c4 = threadIdx.x * 4;      // channel base (float4)
    const float neg = *negp;

    const int head = rel_ids[br * 2 + 0];
    const int tail = rel_ids[br * 2 + 1];
    const int sb = b * NS_;
    const int hs = span_ids[(sb + head) * 2 + 0];
    const int he = span_ids[(sb + head) * 2 + 1];
    const int ts = span_ids[(sb + tail) * 2 + 0];
    const int te = span_ids[(sb + tail) * 2 + 1];

    float* row = g_rel + (size_t)br * DIN;
    float4 hv = *(const float4*)(spans + (size_t)(sb + head) * H_ + c4);
    float4 tv = *(const float4*)(spans + (size_t)(sb + tail) * H_ + c4);
    hv.x = tf32r(hv.x); hv.y = tf32r(hv.y); hv.z = tf32r(hv.z); hv.w = tf32r(hv.w);
    tv.x = tf32r(tv.x); tv.y = tf32r(tv.y); tv.z = tf32r(tv.z); tv.w = tf32r(tv.w);
    *(float4*)(row + c4)       = hv;
    *(float4*)(row + H_ + c4)  = tv;

    const int lo = min(he, te);
    const int hi = max(hs, ts);

    int s1 = min(max(hs, lo), hi), e1 = min(max(he, lo), hi);
    int s2 = min(max(ts, lo), hi), e2 = min(max(te, lo), hi);
    if (s2 < s1) { int t = s1; s1 = s2; s2 = t; t = e1; e1 = e2; e2 = t; }
    if (s2 < e1) { e1 = max(e1, e2); s2 = e1; e2 = e1; }

    const float4* tb4 = (const float4*)(tok + (size_t)b * S_ * H_ + c4);
    const float4* bb4 = (const float4*)(g_blkmax + (size_t)b * NBLK * H_ + c4);
    Acc2 ac;
    ac.a0 = make_float4(neg, neg, neg, neg);
    ac.a1 = ac.a0;

    const int seg_a[3] = { lo, e1, e2 };
    const int seg_b[3] = { s1, s2, hi };
    #pragma unroll
    for (int s = 0; s < 3; s++) {
        int a = seg_a[s], bnd = seg_b[s];
        if (a >= bnd) continue;
        int a16 = (a + 15) & ~15;
        int b16 = bnd & ~15;
        if (a16 >= b16) {
            scan_tokens(ac, tb4, a, bnd);
        } else {
            scan_tokens(ac, tb4, a, a16);
            scan_blocks(ac, bb4, a16 >> 4, b16 >> 4);
            scan_tokens(ac, tb4, b16, bnd);
        }
    }

    float4 m = f4max(ac.a0, ac.a1);
    const int myneg = (m.x == neg) & (m.y == neg) & (m.z == neg) & (m.w == neg);
    const int allneg = __syncthreads_and(myneg);
    float4 o;
    if (allneg) {
        o = make_float4(0.0f, 0.0f, 0.0f, 0.0f);
    } else {
        o = make_float4(tf32r(m.x), tf32r(m.y), tf32r(m.z), tf32r(m.w));
    }
    *(float4*)(row + 2 * H_ + c4) = o;
}

// ---------------------------------------------------------------------------
// tf32 tensor-core GEMM (mma.sync m16n8k8), cp.async double-buffered,
// dynamic shared memory (tile 128x128 exceeds the static budget).
// All operands PRE-ROUNDED to tf32 -> fragment loads are raw LDS.
// SPLITK: blockIdx.z picks a K-chunk; partial -> C + z*M*N.
// ROUND_OUT: round stored outputs to tf32 (feeding the next GEMM).
// ---------------------------------------------------------------------------
__device__ __forceinline__ void cp_async16(uint32_t dst, const void* src) {
    asm volatile("cp.async.cg.shared.global [%0], [%1], 16;\n"
                 :: "r"(dst), "l"(src));
}

__device__ __forceinline__ void mma_tf32(float* c, const uint32_t* a, const uint32_t* b) {
    asm volatile(
        "mma.sync.aligned.m16n8k8.row.col.f32.tf32.tf32.f32 "
        "{%0,%1,%2,%3}, {%4,%5,%6,%7}, {%8,%9}, {%0,%1,%2,%3};"
        : "+f"(c[0]), "+f"(c[1]), "+f"(c[2]), "+f"(c[3])
        : "r"(a[0]), "r"(a[1]), "r"(a[2]), "r"(a[3]), "r"(b[0]), "r"(b[1]));
}

template <int BM, int BN, int BK, int WM, int WN, bool RELU, bool SPLITK, bool ROUND_OUT>
__global__ void __launch_bounds__((BM / WM) * (BN / WN) * 32)
k_tgemm(const float* __restrict__ A, const float* __restrict__ Bw,
        const float* __restrict__ bias, float* __restrict__ C,
        int M, int N, int K, int Ksplit) {
    constexpr int WARPS_M = BM / WM;
    constexpr int WARPS_N = BN / WN;
    constexpr int NT = WARPS_M * WARPS_N * 32;
    constexpr int ASTR = BK + 4;          // float stride; (BK+4)*4 % 16 == 0
    constexpr int BSTR = BN + 8;          // conflict-free fragment reads
    constexpr int MT = WM / 16;
    constexpr int NTL = WN / 8;
    constexpr int LDA = (BM * BK / 4) / NT;   // float4 loads per thread (A)
    constexpr int LDB = (BK * BN / 4) / NT;   // float4 loads per thread (B)
    constexpr int ASZ = BM * ASTR;
    constexpr int BSZ = BK * BSTR;

    extern __shared__ float dsm[];
    float* As = dsm;                 // [2][ASZ]
    float* Bs = dsm + 2 * ASZ;       // [2][BSZ]

    const int tid = threadIdx.x;
    const int bm = blockIdx.y * BM;
    const int bn = blockIdx.x * BN;
    const int k0 = SPLITK ? blockIdx.z * Ksplit : 0;
    if (SPLITK) C += (size_t)blockIdx.z * M * N;
    const int wid = tid >> 5, lane = tid & 31;
    const int gid = lane >> 2, tig = lane & 3;
    const int wm0 = (wid % WARPS_M) * WM;
    const int wn0 = (wid / WARPS_M) * WN;

    float acc[MT][NTL][4];
    #pragma unroll
    for (int i = 0; i < MT; i++)
        #pragma unroll
        for (int j = 0; j < NTL; j++)
            #pragma unroll
            for (int q = 0; q < 4; q++) acc[i][j][q] = 0.0f;

    auto load_stage = [&](int s, int kk) {
        #pragma unroll
        for (int j = 0; j < LDA; j++) {
            int i = tid + j * NT;
            int r = i / (BK / 4), c4 = i % (BK / 4);
            cp_async16((uint32_t)__cvta_generic_to_shared(&As[s * ASZ + r * ASTR + c4 * 4]),
                       A + (size_t)(bm + r) * K + kk + c4 * 4);
        }
        #pragma unroll
        for (int j = 0; j < LDB; j++) {
            int i = tid + j * NT;
            int r = i / (BN / 4), c4 = i % (BN / 4);
            cp_async16((uint32_t)__cvta_generic_to_shared(&Bs[s * BSZ + r * BSTR + c4 * 4]),
                       Bw + (size_t)(kk + r) * N + bn + c4 * 4);
        }
        asm volatile("cp.async.commit_group;\n" ::: "memory");
    };

    const int nk = Ksplit / BK;
    load_stage(0, k0);
    int s = 0;
    for (int kk = 0; kk < nk; kk++) {
        if (kk + 1 < nk) {
            load_stage(s ^ 1, k0 + (kk + 1) * BK);
            asm volatile("cp.async.wait_group 1;\n" ::: "memory");
        } else {
            asm volatile("cp.async.wait_group 0;\n" ::: "memory");
        }
        __syncthreads();

        #pragma unroll
        for (int k8 = 0; k8 < BK / 8; k8++) {
            uint32_t af[MT][4];
            uint32_t bf[NTL][2];
            #pragma unroll
            for (int mt = 0; mt < MT; mt++) {
                const uint32_t* p = (const uint32_t*)
                    &As[s * ASZ + (wm0 + mt * 16 + gid) * ASTR + k8 * 8 + tig];
                af[mt][0] = p[0];
                af[mt][1] = p[8 * ASTR];
                af[mt][2] = p[4];
                af[mt][3] = p[8 * ASTR + 4];
            }
            #pragma unroll
            for (int nt = 0; nt < NTL; nt++) {
                const uint32_t* p = (const uint32_t*)
                    &Bs[s * BSZ + (k8 * 8 + tig) * BSTR + wn0 + nt * 8 + gid];
                bf[nt][0] = p[0];
                bf[nt][1] = p[4 * BSTR];
            }
            #pragma unroll
            for (int mt = 0; mt < MT; mt++)
                #pragma unroll
                for (int nt = 0; nt < NTL; nt++)
                    mma_tf32(acc[mt][nt], af[mt], bf[nt]);
        }
        __syncthreads();
        s ^= 1;
    }

    // Epilogue: (bias +ReLU) unless SPLITK partial; optional tf32 rounding.
    #pragma unroll
    for (int mt = 0; mt < MT; mt++) {
        const int m0 = bm + wm0 + mt * 16 + gid;
        #pragma unroll
        for (int nt = 0; nt < NTL; nt++) {
            const int n0 = bn + wn0 + nt * 8 + 2 * tig;
            float bv0 = 0.0f, bv1 = 0.0f;
            if (!SPLITK) { bv0 = bias[n0]; bv1 = bias[n0 + 1]; }
            float v0 = acc[mt][nt][0] + bv0;
            float v1 = acc[mt][nt][1] + bv1;
            float v2 = acc[mt][nt][2] + bv0;
            float v3 = acc[mt][nt][3] + bv1;
            if (RELU) {
                v0 = fmaxf(v0, 0.0f); v1 = fmaxf(v1, 0.0f);
                v2 = fmaxf(v2, 0.0f); v3 = fmaxf(v3, 0.0f);
            }
            if (ROUND_OUT) {
                v0 = tf32r(v0); v1 = tf32r(v1); v2 = tf32r(v2); v3 = tf32r(v3);
            }
            *(float2*)(C + (size_t)m0 * N + n0)       = make_float2(v0, v1);
            *(float2*)(C + (size_t)(m0 + 8) * N + n0) = make_float2(v2, v3);
        }
    }
}

// ---------------------------------------------------------------------------
// Split-K reduce: out = sum_s part[s] + bias   (fixed order -> deterministic)
// ---------------------------------------------------------------------------
__global__ void k_reduce(const float* __restrict__ part,
                         const float* __restrict__ bias,
                         float* __restrict__ out) {
    const size_t i4 = (size_t)blockIdx.x * blockDim.x + threadIdx.x;
    const size_t e = i4 * 4;
    const int n0 = (int)(e & (H_ - 1));
    float4 b = *(const float4*)(bias + n0);
    float4 r = make_float4(b.x, b.y, b.z, b.w);
    #pragma unroll
    for (int s = 0; s < KSPLIT; s++) {
        float4 a = *(const float4*)(part + (size_t)s * MN + e);
        r.x += a.x; r.y += a.y; r.z += a.z; r.w += a.w;
    }
    *(float4*)(out + e) = r;
}

// ---------------------------------------------------------------------------
// Input order per setup_inputs dict:
//  0 token_reps f32 (B,S,H)      1 token_masks bool (B,S)   2 span_reps f32 (B,NS,H)
//  3 span_ids  i32 (B,NS,2)      4 rel_ids   i32 (B,NR,2)   5 rel_masks bool (B,NR)
//  6 neg_limit f32 scalar        7 W1 (768,3072)  8 b1 (3072,)
//  9 W2 (3072,256)              10 b2 (256,)
// Output: f32 (B, NR, H) = 524288 (2*512*256)
// ---------------------------------------------------------------------------
extern "C" void kernel_launch(void* const* d_in, const int* in_sizes, int n_in,
                              void* d_out, int out_size) {
    const float* tok   = (const float*)d_in[0];
    const float* spans = (const float*)d_in[2];
    const int*   sids  = (const int*)d_in[3];
    const int*   rids  = (const int*)d_in[4];
    const float* negp  = (const float*)d_in[6];
    const float* W1    = (const float*)d_in[7];
    const float* b1    = (const float*)d_in[8];
    const float* W2    = (const float*)d_in[9];
    const float* b2    = (const float*)d_in[10];
    float* out = (float*)d_out;

    float *rel, *hbuf, *part, *w1r, *w2r;
    cudaGetSymbolAddress((void**)&rel,  g_rel);
    cudaGetSymbolAddress((void**)&hbuf, g_h);
    cudaGetSymbolAddress((void**)&part, g_part);
    cudaGetSymbolAddress((void**)&w1r,  g_w1r);
    cudaGetSymbolAddress((void**)&w2r,  g_w2r);

    // GEMM smem: 2*(128*36) + 2*(32*136) floats = 71680 bytes
    constexpr int GSMEM = (2 * 128 * 36 + 2 * 32 * 136) * 4;
    cudaFuncSetAttribute(k_tgemm<128, 128, 32, 32, 64, true, false, true>,
                         cudaFuncAttributeMaxDynamicSharedMemorySize, GSMEM);
    cudaFuncSetAttribute(k_tgemm<128, 128, 32, 32, 64, false, true, false>,
                         cudaFuncAttributeMaxDynamicSharedMemorySize, GSMEM);

    // Pre-round weights to tf32 (one shot, removes all inner-loop cvts)
    k_round<<<(DIN * DFF / 4) / 256, 256>>>(W1, w1r);
    k_round<<<(DFF * H_ / 4) / 256, 256>>>(W2, w2r);

    k_blkmax<<<B_ * NBLK, 64>>>(tok);
    k_rel<<<B_ * NR_, 64>>>(tok, spans, sids, rids, negp);

    // GEMM1: (2048 x 768) @ (768 x 3072) + b1, ReLU -> 384 CTAs, 128x128 tiles
    k_tgemm<128, 128, 32, 32, 64, true, false, true>
        <<<dim3(DFF / 128, (B_ * NR_) / 128), 256, GSMEM>>>(rel, w1r, b1, hbuf,
                                                            B_ * NR_, DFF, DIN, DIN);
    // GEMM2: (2048 x 3072) @ (3072 x 256), split-K=8 -> 256 CTAs, 128x128 tiles
    k_tgemm<128, 128, 32, 32, 64, false, true, false>
        <<<dim3(H_ / 128, (B_ * NR_) / 128, KSPLIT), 256, GSMEM>>>(hbuf, w2r, nullptr,
                                                                   part, B_ * NR_, H_,
                                                                   DFF, DFF / KSPLIT);
    // Reduce partials + bias -> out
    k_reduce<<<(int)(MN / 4 / 256), 256>>>(part, b2, out);
}

// round 11
// speedup vs baseline: 1.0131x; 1.0131x over previous
#include <cuda_runtime.h>
#include <cstdint>
#include <cstddef>

// Problem constants (fixed by the reference's setup_inputs)
#define B_   2
#define S_   2048
#define H_   256
#define NS_  512
#define NR_  512
#define DIN  768    // 3*H
#define DFF  3072   // 4*DIN
#define NBLK (S_ / 16)   // 128 block-maxima per batch row
#define KSPLIT 8
#define MN   ((size_t)B_ * NR_ * H_)     // 524288 output elems

// Scratch (static device globals: allocation-free per harness rules)
__device__ float g_rel[(size_t)B_ * NR_ * DIN];        // 6 MB   rel_reps (tf32-rounded)
__device__ float g_h[(size_t)B_ * NR_ * DFF];          // 24 MB  hidden (tf32-rounded)
__device__ float g_blkmax[(size_t)B_ * NBLK * H_];     // 256 KB 16-token block maxima
__device__ float g_part[(size_t)KSPLIT * MN];          // 16 MB  split-K partials
__device__ float g_w1r[(size_t)DIN * DFF];             // 9.4 MB W1 tf32-rounded
__device__ float g_w2r[(size_t)DFF * H_];              // 3 MB   W2 tf32-rounded

__device__ __forceinline__ uint32_t f2tf32(float f) {
    uint32_t r;
    asm("cvt.rna.tf32.f32 %0, %1;" : "=r"(r) : "f"(f));
    return r;
}
__device__ __forceinline__ float tf32r(float f) { return __uint_as_float(f2tf32(f)); }

// ---------------------------------------------------------------------------
// Weight pre-round: w_out = tf32_round(w_in), float4 vectorized.
// ---------------------------------------------------------------------------
__global__ void k_round(const float* __restrict__ in, float* __restrict__ out) {
    const size_t i = ((size_t)blockIdx.x * blockDim.x + threadIdx.x) * 4;
    float4 v = *(const float4*)(in + i);
    v.x = tf32r(v.x); v.y = tf32r(v.y); v.z = tf32r(v.z); v.w = tf32r(v.w);
    *(float4*)(out + i) = v;
}

// ---------------------------------------------------------------------------
// Kernel 0: per-16-token block maxima of token_reps. 256 threads = channels
// (high occupancy version — R8 showed TLP beats ILP for these kernels).
// ---------------------------------------------------------------------------
__global__ void k_blkmax(const float* __restrict__ tok,
                         const float* __restrict__ negp) {
    const int blk = blockIdx.x;
    const int h = threadIdx.x;
    const float* p = tok + (size_t)blk * 16 * H_ + h;
    float m0 = p[0], m1 = p[H_];
    #pragma unroll
    for (int i = 2; i < 16; i += 2) {
        float v0 = p[(size_t)i * H_];
        float v1 = p[(size_t)(i + 1) * H_];
        m0 = fmaxf(m0, v0);
        m1 = fmaxf(m1, v1);
    }
    g_blkmax[(size_t)blk * H_ + h] = fmaxf(m0, m1);
}

// ---------------------------------------------------------------------------
// Kernel 1: rel_reps = [head | tail | context-maxpool], tf32-rounded at store.
// 256 threads/relation (one channel each: max occupancy) PLUS paired loads
// into 2 independent accumulators (ILP). R7 had the occupancy but not the
// ILP; R8 had the ILP but killed the occupancy — this has both.
// ---------------------------------------------------------------------------
__global__ void __launch_bounds__(256)
k_rel(const float* __restrict__ tok,
      const float* __restrict__ spans,
      const int* __restrict__ span_ids,
      const int* __restrict__ rel_ids,
      const float* __restrict__ negp) {
    const int br = blockIdx.x;           // b*NR + r
    const int b = br >> 9;
    const int h = threadIdx.x;
    const float neg = *negp;

    const int head = rel_ids[br * 2 + 0];
    const int tail = rel_ids[br * 2 + 1];
    const int sb = b * NS_;
    const int hs = span_ids[(sb + head) * 2 + 0];
    const int he = span_ids[(sb + head) * 2 + 1];
    const int ts = span_ids[(sb + tail) * 2 + 0];
    const int te = span_ids[(sb + tail) * 2 + 1];

    float* row = g_rel + (size_t)br * DIN;
    row[h]       = tf32r(spans[(size_t)(sb + head) * H_ + h]);
    row[H_ + h]  = tf32r(spans[(size_t)(sb + tail) * H_ + h]);

    const int lo = min(he, te);
    const int hi = max(hs, ts);

    int s1 = min(max(hs, lo), hi), e1 = min(max(he, lo), hi);
    int s2 = min(max(ts, lo), hi), e2 = min(max(te, lo), hi);
    if (s2 < s1) { int t = s1; s1 = s2; s2 = t; t = e1; e1 = e2; e2 = t; }
    if (s2 < e1) { e1 = max(e1, e2); s2 = e1; e2 = e1; }

    const float* tb = tok + (size_t)b * S_ * H_ + h;
    const float* bb = g_blkmax + (size_t)b * NBLK * H_ + h;
    float m0 = neg, m1 = neg;

    const int seg_a[3] = { lo, e1, e2 };
    const int seg_b[3] = { s1, s2, hi };
    #pragma unroll
    for (int s = 0; s < 3; s++) {
        int a = seg_a[s], bnd = seg_b[s];
        if (a >= bnd) continue;
        int a16 = (a + 15) & ~15;
        int b16 = bnd & ~15;
        if (a16 >= b16) { a16 = bnd; b16 = bnd; }   // tokens-only segment
        // leading edge tokens [a, a16)
        int t = a;
        for (; t + 2 <= a16; t += 2) {
            float v0 = tb[(size_t)t * H_];
            float v1 = tb[(size_t)(t + 1) * H_];
            m0 = fmaxf(m0, v0);
            m1 = fmaxf(m1, v1);
        }
        if (t < a16) m0 = fmaxf(m0, tb[(size_t)t * H_]);
        // interior block maxima [a16/16, b16/16)
        int j = a16 >> 4;
        const int j1 = b16 >> 4;
        for (; j + 4 <= j1; j += 4) {
            float v0 = bb[(size_t)j * H_];
            float v1 = bb[(size_t)(j + 1) * H_];
            float v2 = bb[(size_t)(j + 2) * H_];
            float v3 = bb[(size_t)(j + 3) * H_];
            m0 = fmaxf(m0, fmaxf(v0, v2));
            m1 = fmaxf(m1, fmaxf(v1, v3));
        }
        for (; j + 2 <= j1; j += 2) {
            float v0 = bb[(size_t)j * H_];
            float v1 = bb[(size_t)(j + 1) * H_];
            m0 = fmaxf(m0, v0);
            m1 = fmaxf(m1, v1);
        }
        if (j < j1) m0 = fmaxf(m0, bb[(size_t)j * H_]);
        // trailing edge tokens [b16, bnd)
        t = b16;
        for (; t + 2 <= bnd; t += 2) {
            float v0 = tb[(size_t)t * H_];
            float v1 = tb[(size_t)(t + 1) * H_];
            m0 = fmaxf(m0, v0);
            m1 = fmaxf(m1, v1);
        }
        if (t < bnd) m0 = fmaxf(m0, tb[(size_t)t * H_]);
    }

    const float m = fmaxf(m0, m1);
    const int allneg = __syncthreads_and(m == neg);
    row[2 * H_ + h] = allneg ? 0.0f : tf32r(m);
}

// ---------------------------------------------------------------------------
// tf32 tensor-core GEMM (mma.sync m16n8k8), cp.async double-buffered,
// dynamic shared memory. All operands PRE-ROUNDED to tf32 -> fragment loads
// are raw LDS. SPLITK: blockIdx.z picks a K-chunk; partial -> C + z*M*N.
// ROUND_OUT: round stored outputs to tf32 (feeding the next GEMM).
// ---------------------------------------------------------------------------
__device__ __forceinline__ void cp_async16(uint32_t dst, const void* src) {
    asm volatile("cp.async.cg.shared.global [%0], [%1], 16;\n"
                 :: "r"(dst), "l"(src));
}

__device__ __forceinline__ void mma_tf32(float* c, const uint32_t* a, const uint32_t* b) {
    asm volatile(
        "mma.sync.aligned.m16n8k8.row.col.f32.tf32.tf32.f32 "
        "{%0,%1,%2,%3}, {%4,%5,%6,%7}, {%8,%9}, {%0,%1,%2,%3};"
        : "+f"(c[0]), "+f"(c[1]), "+f"(c[2]), "+f"(c[3])
        : "r"(a[0]), "r"(a[1]), "r"(a[2]), "r"(a[3]), "r"(b[0]), "r"(b[1]));
}

template <int BM, int BN, int BK, int WM, int WN, bool RELU, bool SPLITK, bool ROUND_OUT>
__global__ void __launch_bounds__((BM / WM) * (BN / WN) * 32)
k_tgemm(const float* __restrict__ A, const float* __restrict__ Bw,
        const float* __restrict__ bias, float* __restrict__ C,
        int M, int N, int K, int Ksplit) {
    constexpr int WARPS_M = BM / WM;
    constexpr int WARPS_N = BN / WN;
    constexpr int NT = WARPS_M * WARPS_N * 32;
    constexpr int ASTR = BK + 4;          // float stride; (BK+4)*4 % 16 == 0
    constexpr int BSTR = BN + 8;          // conflict-free fragment reads
    constexpr int MT = WM / 16;
    constexpr int NTL = WN / 8;
    constexpr int LDA = (BM * BK / 4) / NT;   // float4 loads per thread (A)
    constexpr int LDB = (BK * BN / 4) / NT;   // float4 loads per thread (B)
    constexpr int ASZ = BM * ASTR;
    constexpr int BSZ = BK * BSTR;

    extern __shared__ float dsm[];
    float* As = dsm;                 // [2][ASZ]
    float* Bs = dsm + 2 * ASZ;       // [2][BSZ]

    const int tid = threadIdx.x;
    const int bm = blockIdx.y * BM;
    const int bn = blockIdx.x * BN;
    const int k0 = SPLITK ? blockIdx.z * Ksplit : 0;
    if (SPLITK) C += (size_t)blockIdx.z * M * N;
    const int wid = tid >> 5, lane = tid & 31;
    const int gid = lane >> 2, tig = lane & 3;
    const int wm0 = (wid % WARPS_M) * WM;
    const int wn0 = (wid / WARPS_M) * WN;

    float acc[MT][NTL][4];
    #pragma unroll
    for (int i = 0; i < MT; i++)
        #pragma unroll
        for (int j = 0; j < NTL; j++)
            #pragma unroll
            for (int q = 0; q < 4; q++) acc[i][j][q] = 0.0f;

    auto load_stage = [&](int s, int kk) {
        #pragma unroll
        for (int j = 0; j < LDA; j++) {
            int i = tid + j * NT;
            int r = i / (BK / 4), c4 = i % (BK / 4);
            cp_async16((uint32_t)__cvta_generic_to_shared(&As[s * ASZ + r * ASTR + c4 * 4]),
                       A + (size_t)(bm + r) * K + kk + c4 * 4);
        }
        #pragma unroll
        for (int j = 0; j < LDB; j++) {
            int i = tid + j * NT;
            int r = i / (BN / 4), c4 = i % (BN / 4);
            cp_async16((uint32_t)__cvta_generic_to_shared(&Bs[s * BSZ + r * BSTR + c4 * 4]),
                       Bw + (size_t)(kk + r) * N + bn + c4 * 4);
        }
        asm volatile("cp.async.commit_group;\n" ::: "memory");
    };

    const int nk = Ksplit / BK;
    load_stage(0, k0);
    int s = 0;
    for (int kk = 0; kk < nk; kk++) {
        if (kk + 1 < nk) {
            load_stage(s ^ 1, k0 + (kk + 1) * BK);
            asm volatile("cp.async.wait_group 1;\n" ::: "memory");
        } else {
            asm volatile("cp.async.wait_group 0;\n" ::: "memory");
        }
        __syncthreads();

        #pragma unroll
        for (int k8 = 0; k8 < BK / 8; k8++) {
            uint32_t af[MT][4];
            uint32_t bf[NTL][2];
            #pragma unroll
            for (int mt = 0; mt < MT; mt++) {
                const uint32_t* p = (const uint32_t*)
                    &As[s * ASZ + (wm0 + mt * 16 + gid) * ASTR + k8 * 8 + tig];
                af[mt][0] = p[0];
                af[mt][1] = p[8 * ASTR];
                af[mt][2] = p[4];
                af[mt][3] = p[8 * ASTR + 4];
            }
            #pragma unroll
            for (int nt = 0; nt < NTL; nt++) {
                const uint32_t* p = (const uint32_t*)
                    &Bs[s * BSZ + (k8 * 8 + tig) * BSTR + wn0 + nt * 8 + gid];
                bf[nt][0] = p[0];
                bf[nt][1] = p[4 * BSTR];
            }
            #pragma unroll
            for (int mt = 0; mt < MT; mt++)
                #pragma unroll
                for (int nt = 0; nt < NTL; nt++)
                    mma_tf32(acc[mt][nt], af[mt], bf[nt]);
        }
        __syncthreads();
        s ^= 1;
    }

    // Epilogue: (bias +ReLU) unless SPLITK partial; optional tf32 rounding.
    #pragma unroll
    for (int mt = 0; mt < MT; mt++) {
        const int m0 = bm + wm0 + mt * 16 + gid;
        #pragma unroll
        for (int nt = 0; nt < NTL; nt++) {
            const int n0 = bn + wn0 + nt * 8 + 2 * tig;
            float bv0 = 0.0f, bv1 = 0.0f;
            if (!SPLITK) { bv0 = bias[n0]; bv1 = bias[n0 + 1]; }
            float v0 = acc[mt][nt][0] + bv0;
            float v1 = acc[mt][nt][1] + bv1;
            float v2 = acc[mt][nt][2] + bv0;
            float v3 = acc[mt][nt][3] + bv1;
            if (RELU) {
                v0 = fmaxf(v0, 0.0f); v1 = fmaxf(v1, 0.0f);
                v2 = fmaxf(v2, 0.0f); v3 = fmaxf(v3, 0.0f);
            }
            if (ROUND_OUT) {
                v0 = tf32r(v0); v1 = tf32r(v1); v2 = tf32r(v2); v3 = tf32r(v3);
            }
            *(float2*)(C + (size_t)m0 * N + n0)       = make_float2(v0, v1);
            *(float2*)(C + (size_t)(m0 + 8) * N + n0) = make_float2(v2, v3);
        }
    }
}

// ---------------------------------------------------------------------------
// Split-K reduce: out = sum_s part[s] + bias   (fixed order -> deterministic)
// ---------------------------------------------------------------------------
__global__ void k_reduce(const float* __restrict__ part,
                         const float* __restrict__ bias,
                         float* __restrict__ out) {
    const size_t i4 = (size_t)blockIdx.x * blockDim.x + threadIdx.x;
    const size_t e = i4 * 4;
    const int n0 = (int)(e & (H_ - 1));
    float4 b = *(const float4*)(bias + n0);
    float4 r = make_float4(b.x, b.y, b.z, b.w);
    #pragma unroll
    for (int s = 0; s < KSPLIT; s++) {
        float4 a = *(const float4*)(part + (size_t)s * MN + e);
        r.x += a.x; r.y += a.y; r.z += a.z; r.w += a.w;
    }
    *(float4*)(out + e) = r;
}

// ---------------------------------------------------------------------------
// Input order per setup_inputs dict:
//  0 token_reps f32 (B,S,H)      1 token_masks bool (B,S)   2 span_reps f32 (B,NS,H)
//  3 span_ids  i32 (B,NS,2)      4 rel_ids   i32 (B,NR,2)   5 rel_masks bool (B,NR)
//  6 neg_limit f32 scalar        7 W1 (768,3072)  8 b1 (3072,)
//  9 W2 (3072,256)              10 b2 (256,)
// Output: f32 (B, NR, H) = 524288 (2*512*256)
// ---------------------------------------------------------------------------
extern "C" void kernel_launch(void* const* d_in, const int* in_sizes, int n_in,
                              void* d_out, int out_size) {
    const float* tok   = (const float*)d_in[0];
    const float* spans = (const float*)d_in[2];
    const int*   sids  = (const int*)d_in[3];
    const int*   rids  = (const int*)d_in[4];
    const float* negp  = (const float*)d_in[6];
    const float* W1    = (const float*)d_in[7];
    const float* b1    = (const float*)d_in[8];
    const float* W2    = (const float*)d_in[9];
    const float* b2    = (const float*)d_in[10];
    float* out = (float*)d_out;

    float *rel, *hbuf, *part, *w1r, *w2r;
    cudaGetSymbolAddress((void**)&rel,  g_rel);
    cudaGetSymbolAddress((void**)&hbuf, g_h);
    cudaGetSymbolAddress((void**)&part, g_part);
    cudaGetSymbolAddress((void**)&w1r,  g_w1r);
    cudaGetSymbolAddress((void**)&w2r,  g_w2r);

    // GEMM1: 128x128x32, 4 warps (64x64 warp tiles): smem 2*(128*36+32*136)*4
    constexpr int GSMEM1 = (2 * (128 * 36) + 2 * (32 * 136)) * 4;   // 71680
    // GEMM2: 128x64x32, 8 warps (32x32 warp tiles):  smem 2*(128*36+32*72)*4
    constexpr int GSMEM2 = (2 * (128 * 36) + 2 * (32 * 72)) * 4;    // 55296
    cudaFuncSetAttribute(k_tgemm<128, 128, 32, 64, 64, true, false, true>,
                         cudaFuncAttributeMaxDynamicSharedMemorySize, GSMEM1);
    cudaFuncSetAttribute(k_tgemm<128, 64, 32, 32, 32, false, true, false>,
                         cudaFuncAttributeMaxDynamicSharedMemorySize, GSMEM2);

    // Pre-round weights to tf32 (one shot, removes all inner-loop cvts)
    k_round<<<(DIN * DFF / 4) / 256, 256>>>(W1, w1r);
    k_round<<<(DFF * H_ / 4) / 256, 256>>>(W2, w2r);

    k_blkmax<<<B_ * NBLK, H_>>>(tok, negp);
    k_rel<<<B_ * NR_, H_>>>(tok, spans, sids, rids, negp);

    // GEMM1: (2048 x 768) @ (768 x 3072) + b1, ReLU
    //   384 CTAs, 128 threads, 64x64 warp tiles (1:1 LDS:MMA issue ratio)
    k_tgemm<128, 128, 32, 64, 64, true, false, true>
        <<<dim3(DFF / 128, (B_ * NR_) / 128), 128, GSMEM1>>>(rel, w1r, b1, hbuf,
                                                             B_ * NR_, DFF, DIN, DIN);
    // GEMM2: (2048 x 3072) @ (3072 x 256), split-K=8 -> 512 CTAs (R7 proven config)
    k_tgemm<128, 64, 32, 32, 32, false, true, false>
        <<<dim3(H_ / 64, (B_ * NR_) / 128, KSPLIT), 256, GSMEM2>>>(hbuf, w2r, nullptr,
                                                                   part, B_ * NR_, H_,
                                                                   DFF, DFF / KSPLIT);
    // Reduce partials + bias -> out
    k_reduce<<<(int)(MN / 4 / 256), 256>>>(part, b2, out);
}

// round 12
// speedup vs baseline: 1.0719x; 1.0580x over previous
#include <cuda_runtime.h>
#include <cstdint>
#include <cstddef>

// Problem constants (fixed by the reference's setup_inputs)
#define B_   2
#define S_   2048
#define H_   256
#define NS_  512
#define NR_  512
#define DIN  768    // 3*H
#define DFF  3072   // 4*DIN
#define NBLK (S_ / 16)    // 128 fine (16-token) blocks per batch row
#define NCBLK (S_ / 256)  // 8 coarse (256-token) blocks per batch row
#define KSPLIT 8
#define MN   ((size_t)B_ * NR_ * H_)     // 524288 output elems

// Scratch (static device globals: allocation-free per harness rules)
__device__ float g_rel[(size_t)B_ * NR_ * DIN];        // 6 MB   rel_reps (tf32-rounded)
__device__ float g_h[(size_t)B_ * NR_ * DFF];          // 24 MB  hidden (tf32-rounded)
__device__ float g_blkmax[(size_t)B_ * NBLK * H_];     // 256 KB fine block maxima
__device__ float g_blkmax2[(size_t)B_ * NCBLK * H_];   // 16 KB  coarse block maxima
__device__ float g_part[(size_t)KSPLIT * MN];          // 16 MB  split-K partials
__device__ float g_w1r[(size_t)DIN * DFF];             // 9.4 MB W1 tf32-rounded
__device__ float g_w2r[(size_t)DFF * H_];              // 3 MB   W2 tf32-rounded

__device__ __forceinline__ uint32_t f2tf32(float f) {
    uint32_t r;
    asm("cvt.rna.tf32.f32 %0, %1;" : "=r"(r) : "f"(f));
    return r;
}
__device__ __forceinline__ float tf32r(float f) { return __uint_as_float(f2tf32(f)); }

// ---------------------------------------------------------------------------
// Weight pre-round (both W1 and W2 in one launch): tf32_round, float4 vec.
// ---------------------------------------------------------------------------
__global__ void k_round(const float* __restrict__ in1, float* __restrict__ out1,
                        size_t n1,
                        const float* __restrict__ in2, float* __restrict__ out2) {
    size_t i = ((size_t)blockIdx.x * blockDim.x + threadIdx.x) * 4;
    const float* in = in1;
    float* out = out1;
    if (i >= n1) { i -= n1; in = in2; out = out2; }
    float4 v = *(const float4*)(in + i);
    v.x = tf32r(v.x); v.y = tf32r(v.y); v.z = tf32r(v.z); v.w = tf32r(v.w);
    *(float4*)(out + i) = v;
}

// ---------------------------------------------------------------------------
// Kernel 0: per-16-token (fine) block maxima of token_reps.
// ---------------------------------------------------------------------------
__global__ void k_blkmax(const float* __restrict__ tok,
                         const float* __restrict__ negp) {
    const int blk = blockIdx.x;
    const int h = threadIdx.x;
    float m = *negp;
    const float* p = tok + (size_t)blk * 16 * H_ + h;
    #pragma unroll
    for (int i = 0; i < 16; i++) m = fmaxf(m, p[(size_t)i * H_]);
    g_blkmax[(size_t)blk * H_ + h] = m;
}

// ---------------------------------------------------------------------------
// Kernel 0b: coarse (256-token) block maxima = max over 16 fine blocks.
// grid = B_*NCBLK (16 blocks), 256 threads.
// ---------------------------------------------------------------------------
__global__ void k_blkmax2(void) {
    const int cb = blockIdx.x;           // b*NCBLK + c
    const int h = threadIdx.x;
    const float* p = g_blkmax + (size_t)cb * 16 * H_ + h;
    float m = p[0];
    #pragma unroll
    for (int i = 1; i < 16; i++) m = fmaxf(m, p[(size_t)i * H_]);
    g_blkmax2[(size_t)cb * H_ + h] = m;
}

// ---------------------------------------------------------------------------
// Kernel 1: rel_reps = [head | tail | context-maxpool], tf32-rounded at store.
// 256 threads/relation, one channel each (R7-proven structure; R8/R9 showed
// ILP restructuring only hurts). New: two-level block maxima — interior of
// each segment uses 256-token coarse blocks, then 16-token fine blocks, then
// edge tokens. Cuts per-thread trip count ~72 -> ~25.
// ---------------------------------------------------------------------------
__global__ void __launch_bounds__(256)
k_rel(const float* __restrict__ tok,
      const float* __restrict__ spans,
      const int* __restrict__ span_ids,
      const int* __restrict__ rel_ids,
      const float* __restrict__ negp) {
    const int br = blockIdx.x;           // b*NR + r
    const int b = br >> 9;
    const int h = threadIdx.x;
    const float neg = *negp;

    const int head = rel_ids[br * 2 + 0];
    const int tail = rel_ids[br * 2 + 1];
    const int sb = b * NS_;
    const int hs = span_ids[(sb + head) * 2 + 0];
    const int he = span_ids[(sb + head) * 2 + 1];
    const int ts = span_ids[(sb + tail) * 2 + 0];
    const int te = span_ids[(sb + tail) * 2 + 1];

    float* row = g_rel + (size_t)br * DIN;
    row[h]       = tf32r(spans[(size_t)(sb + head) * H_ + h]);
    row[H_ + h]  = tf32r(spans[(size_t)(sb + tail) * H_ + h]);

    const int lo = min(he, te);
    const int hi = max(hs, ts);

    int s1 = min(max(hs, lo), hi), e1 = min(max(he, lo), hi);
    int s2 = min(max(ts, lo), hi), e2 = min(max(te, lo), hi);
    if (s2 < s1) { int t = s1; s1 = s2; s2 = t; t = e1; e1 = e2; e2 = t; }
    if (s2 < e1) { e1 = max(e1, e2); s2 = e1; e2 = e1; }

    const float* tb  = tok + (size_t)b * S_ * H_ + h;
    const float* bb  = g_blkmax + (size_t)b * NBLK * H_ + h;
    const float* cbb = g_blkmax2 + (size_t)b * NCBLK * H_ + h;
    float m = neg;

    const int seg_a[3] = { lo, e1, e2 };
    const int seg_b[3] = { s1, s2, hi };
    #pragma unroll
    for (int s = 0; s < 3; s++) {
        const int a = seg_a[s], bnd = seg_b[s];
        if (a >= bnd) continue;
        int a16 = (a + 15) & ~15;
        int b16 = bnd & ~15;
        if (a16 >= b16) {
            // tokens-only segment
            for (int t = a; t < bnd; t++) m = fmaxf(m, tb[(size_t)t * H_]);
            continue;
        }
        // leading edge tokens [a, a16)
        for (int t = a; t < a16; t++) m = fmaxf(m, tb[(size_t)t * H_]);
        // fine-block range [j0, j1)
        const int j0 = a16 >> 4, j1 = b16 >> 4;
        const int jc0 = (j0 + 15) & ~15;     // coarse-aligned (16 fine = 256 tok)
        const int jc1 = j1 & ~15;
        if (jc0 >= jc1) {
            for (int j = j0; j < j1; j++) m = fmaxf(m, bb[(size_t)j * H_]);
        } else {
            for (int j = j0; j < jc0; j++) m = fmaxf(m, bb[(size_t)j * H_]);
            for (int c = (jc0 >> 4); c < (jc1 >> 4); c++)
                m = fmaxf(m, cbb[(size_t)c * H_]);
            for (int j = jc1; j < j1; j++) m = fmaxf(m, bb[(size_t)j * H_]);
        }
        // trailing edge tokens [b16, bnd)
        for (int t = b16; t < bnd; t++) m = fmaxf(m, tb[(size_t)t * H_]);
    }

    const int allneg = __syncthreads_and(m == neg);
    row[2 * H_ + h] = allneg ? 0.0f : tf32r(m);
}

// ---------------------------------------------------------------------------
// tf32 tensor-core GEMM (mma.sync m16n8k8), cp.async double-buffered,
// dynamic shared memory. All operands PRE-ROUNDED to tf32 -> fragment loads
// are raw LDS. SPLITK: blockIdx.z picks a K-chunk; partial -> C + z*M*N.
// ROUND_OUT: round stored outputs to tf32 (feeding the next GEMM).
// (Exact R7-proven configuration and instantiations.)
// ---------------------------------------------------------------------------
__device__ __forceinline__ void cp_async16(uint32_t dst, const void* src) {
    asm volatile("cp.async.cg.shared.global [%0], [%1], 16;\n"
                 :: "r"(dst), "l"(src));
}

__device__ __forceinline__ void mma_tf32(float* c, const uint32_t* a, const uint32_t* b) {
    asm volatile(
        "mma.sync.aligned.m16n8k8.row.col.f32.tf32.tf32.f32 "
        "{%0,%1,%2,%3}, {%4,%5,%6,%7}, {%8,%9}, {%0,%1,%2,%3};"
        : "+f"(c[0]), "+f"(c[1]), "+f"(c[2]), "+f"(c[3])
        : "r"(a[0]), "r"(a[1]), "r"(a[2]), "r"(a[3]), "r"(b[0]), "r"(b[1]));
}

template <int BM, int BN, int BK, int WM, int WN, bool RELU, bool SPLITK, bool ROUND_OUT>
__global__ void __launch_bounds__((BM / WM) * (BN / WN) * 32)
k_tgemm(const float* __restrict__ A, const float* __restrict__ Bw,
        const float* __restrict__ bias, float* __restrict__ C,
        int M, int N, int K, int Ksplit) {
    constexpr int WARPS_M = BM / WM;
    constexpr int WARPS_N = BN / WN;
    constexpr int NT = WARPS_M * WARPS_N * 32;
    constexpr int ASTR = BK + 4;          // float stride; (BK+4)*4 % 16 == 0
    constexpr int BSTR = BN + 8;          // conflict-free fragment reads
    constexpr int MT = WM / 16;
    constexpr int NTL = WN / 8;
    constexpr int LDA = (BM * BK / 4) / NT;   // float4 loads per thread (A)
    constexpr int LDB = (BK * BN / 4) / NT;   // float4 loads per thread (B)
    constexpr int ASZ = BM * ASTR;
    constexpr int BSZ = BK * BSTR;

    extern __shared__ float dsm[];
    float* As = dsm;                 // [2][ASZ]
    float* Bs = dsm + 2 * ASZ;       // [2][BSZ]

    const int tid = threadIdx.x;
    const int bm = blockIdx.y * BM;
    const int bn = blockIdx.x * BN;
    const int k0 = SPLITK ? blockIdx.z * Ksplit : 0;
    if (SPLITK) C += (size_t)blockIdx.z * M * N;
    const int wid = tid >> 5, lane = tid & 31;
    const int gid = lane >> 2, tig = lane & 3;
    const int wm0 = (wid % WARPS_M) * WM;
    const int wn0 = (wid / WARPS_M) * WN;

    float acc[MT][NTL][4];
    #pragma unroll
    for (int i = 0; i < MT; i++)
        #pragma unroll
        for (int j = 0; j < NTL; j++)
            #pragma unroll
            for (int q = 0; q < 4; q++) acc[i][j][q] = 0.0f;

    auto load_stage = [&](int s, int kk) {
        #pragma unroll
        for (int j = 0; j < LDA; j++) {
            int i = tid + j * NT;
            int r = i / (BK / 4), c4 = i % (BK / 4);
            cp_async16((uint32_t)__cvta_generic_to_shared(&As[s * ASZ + r * ASTR + c4 * 4]),
                       A + (size_t)(bm + r) * K + kk + c4 * 4);
        }
        #pragma unroll
        for (int j = 0; j < LDB; j++) {
            int i = tid + j * NT;
            int r = i / (BN / 4), c4 = i % (BN / 4);
            cp_async16((uint32_t)__cvta_generic_to_shared(&Bs[s * BSZ + r * BSTR + c4 * 4]),
                       Bw + (size_t)(kk + r) * N + bn + c4 * 4);
        }
        asm volatile("cp.async.commit_group;\n" ::: "memory");
    };

    const int nk = Ksplit / BK;
    load_stage(0, k0);
    int s = 0;
    for (int kk = 0; kk < nk; kk++) {
        if (kk + 1 < nk) {
            load_stage(s ^ 1, k0 + (kk + 1) * BK);
            asm volatile("cp.async.wait_group 1;\n" ::: "memory");
        } else {
            asm volatile("cp.async.wait_group 0;\n" ::: "memory");
        }
        __syncthreads();

        #pragma unroll
        for (int k8 = 0; k8 < BK / 8; k8++) {
            uint32_t af[MT][4];
            uint32_t bf[NTL][2];
            #pragma unroll
            for (int mt = 0; mt < MT; mt++) {
                const uint32_t* p = (const uint32_t*)
                    &As[s * ASZ + (wm0 + mt * 16 + gid) * ASTR + k8 * 8 + tig];
                af[mt][0] = p[0];
                af[mt][1] = p[8 * ASTR];
                af[mt][2] = p[4];
                af[mt][3] = p[8 * ASTR + 4];
            }
            #pragma unroll
            for (int nt = 0; nt < NTL; nt++) {
                const uint32_t* p = (const uint32_t*)
                    &Bs[s * BSZ + (k8 * 8 + tig) * BSTR + wn0 + nt * 8 + gid];
                bf[nt][0] = p[0];
                bf[nt][1] = p[4 * BSTR];
            }
            #pragma unroll
            for (int mt = 0; mt < MT; mt++)
                #pragma unroll
                for (int nt = 0; nt < NTL; nt++)
                    mma_tf32(acc[mt][nt], af[mt], bf[nt]);
        }
        __syncthreads();
        s ^= 1;
    }

    // Epilogue: (bias +ReLU) unless SPLITK partial; optional tf32 rounding.
    #pragma unroll
    for (int mt = 0; mt < MT; mt++) {
        const int m0 = bm + wm0 + mt * 16 + gid;
        #pragma unroll
        for (int nt = 0; nt < NTL; nt++) {
            const int n0 = bn + wn0 + nt * 8 + 2 * tig;
            float bv0 = 0.0f, bv1 = 0.0f;
            if (!SPLITK) { bv0 = bias[n0]; bv1 = bias[n0 + 1]; }
            float v0 = acc[mt][nt][0] + bv0;
            float v1 = acc[mt][nt][1] + bv1;
            float v2 = acc[mt][nt][2] + bv0;
            float v3 = acc[mt][nt][3] + bv1;
            if (RELU) {
                v0 = fmaxf(v0, 0.0f); v1 = fmaxf(v1, 0.0f);
                v2 = fmaxf(v2, 0.0f); v3 = fmaxf(v3, 0.0f);
            }
            if (ROUND_OUT) {
                v0 = tf32r(v0); v1 = tf32r(v1); v2 = tf32r(v2); v3 = tf32r(v3);
            }
            *(float2*)(C + (size_t)m0 * N + n0)       = make_float2(v0, v1);
            *(float2*)(C + (size_t)(m0 + 8) * N + n0) = make_float2(v2, v3);
        }
    }
}

// ---------------------------------------------------------------------------
// Split-K reduce: out = sum_s part[s] + bias   (fixed order -> deterministic)
// ---------------------------------------------------------------------------
__global__ void k_reduce(const float* __restrict__ part,
                         const float* __restrict__ bias,
                         float* __restrict__ out) {
    const size_t i4 = (size_t)blockIdx.x * blockDim.x + threadIdx.x;
    const size_t e = i4 * 4;
    const int n0 = (int)(e & (H_ - 1));
    float4 b = *(const float4*)(bias + n0);
    float4 r = make_float4(b.x, b.y, b.z, b.w);
    #pragma unroll
    for (int s = 0; s < KSPLIT; s++) {
        float4 a = *(const float4*)(part + (size_t)s * MN + e);
        r.x += a.x; r.y += a.y; r.z += a.z; r.w += a.w;
    }
    *(float4*)(out + e) = r;
}

// ---------------------------------------------------------------------------
// Input order per setup_inputs dict:
//  0 token_reps f32 (B,S,H)      1 token_masks bool (B,S)   2 span_reps f32 (B,NS,H)
//  3 span_ids  i32 (B,NS,2)      4 rel_ids   i32 (B,NR,2)   5 rel_masks bool (B,NR)
//  6 neg_limit f32 scalar        7 W1 (768,3072)  8 b1 (3072,)
//  9 W2 (3072,256)              10 b2 (256,)
// Output: f32 (B, NR, H) = 524288 (2*512*256)
// ---------------------------------------------------------------------------
extern "C" void kernel_launch(void* const* d_in, const int* in_sizes, int n_in,
                              void* d_out, int out_size) {
    const float* tok   = (const float*)d_in[0];
    const float* spans = (const float*)d_in[2];
    const int*   sids  = (const int*)d_in[3];
    const int*   rids  = (const int*)d_in[4];
    const float* negp  = (const float*)d_in[6];
    const float* W1    = (const float*)d_in[7];
    const float* b1    = (const float*)d_in[8];
    const float* W2    = (const float*)d_in[9];
    const float* b2    = (const float*)d_in[10];
    float* out = (float*)d_out;

    float *rel, *hbuf, *part, *w1r, *w2r;
    cudaGetSymbolAddress((void**)&rel,  g_rel);
    cudaGetSymbolAddress((void**)&hbuf, g_h);
    cudaGetSymbolAddress((void**)&part, g_part);
    cudaGetSymbolAddress((void**)&w1r,  g_w1r);
    cudaGetSymbolAddress((void**)&w2r,  g_w2r);

    // R7-proven GEMM config: 128x64x32 tiles, 8 warps (32x32 warp tiles)
    constexpr int GSMEM = (2 * (128 * 36) + 2 * (32 * 72)) * 4;   // 55296
    cudaFuncSetAttribute(k_tgemm<128, 64, 32, 32, 32, true, false, true>,
                         cudaFuncAttributeMaxDynamicSharedMemorySize, GSMEM);
    cudaFuncSetAttribute(k_tgemm<128, 64, 32, 32, 32, false, true, false>,
                         cudaFuncAttributeMaxDynamicSharedMemorySize, GSMEM);

    // Pre-round both weight matrices to tf32 in one launch
    constexpr size_t N1 = (size_t)DIN * DFF;
    constexpr size_t N2 = (size_t)DFF * H_;
    k_round<<<(int)((N1 + N2) / 4 / 256), 256>>>(W1, w1r, N1, W2, w2r);

    k_blkmax<<<B_ * NBLK, H_>>>(tok, negp);
    k_blkmax2<<<B_ * NCBLK, H_>>>();
    k_rel<<<B_ * NR_, H_>>>(tok, spans, sids, rids, negp);

    // GEMM1: (2048 x 768) @ (768 x 3072) + b1, ReLU -> 768 CTAs (R7 config)
    k_tgemm<128, 64, 32, 32, 32, true, false, true>
        <<<dim3(DFF / 64, (B_ * NR_) / 128), 256, GSMEM>>>(rel, w1r, b1, hbuf,
                                                           B_ * NR_, DFF, DIN, DIN);
    // GEMM2: (2048 x 3072) @ (3072 x 256), split-K=8 -> 512 CTAs (R7 config)
    k_tgemm<128, 64, 32, 32, 32, false, true, false>
        <<<dim3(H_ / 64, (B_ * NR_) / 128, KSPLIT), 256, GSMEM>>>(hbuf, w2r, nullptr,
                                                                  part, B_ * NR_, H_,
                                                                  DFF, DFF / KSPLIT);
    // Reduce partials + bias -> out
    k_reduce<<<(int)(MN / 4 / 256), 256>>>(part, b2, out);
}